// round 14
// baseline (speedup 1.0000x reference)
#include <cuda_runtime.h>
#include <cstdint>

#define S_    4096
#define D_    64
#define NH    16
#define BM    128
#define BN    128
#define NT    512
#define NTILES (S_/BN)
#define SCALE 0.18033688011112042f   // log2(e)/sqrt(64)

// smem pitches (floats)
#define QP 68
#define KP 68
#define VP 72
#define PP 132

// smem float offsets
#define QS_OFF 0            // Q  128*68 = 8704
#define KS_OFF 8704         // K  128*68 = 8704   (pass-2 K; pass-1 K buf A)
#define PS_OFF 17408        // P  128*132 = 16896 (pass-1 K buf B)
#define VS_OFF 34304        // V  2 x 128*72 = 18432
#define VSTRIDE 9216
#define RS_OFF 52736        // 4 x 128 rowsum partials
#define SMEM_FLOATS 53248   // 212992 B -> 1 CTA/SM

// pre-rounded inputs: Qr = rna(Q*SCALE), Kr/Vr = rna(K/V)
__device__ __align__(16) float Qr[(size_t)NH * S_ * D_];
__device__ __align__(16) float Kr[(size_t)NH * S_ * D_];
__device__ __align__(16) float Vr[(size_t)NH * S_ * D_];

__device__ __forceinline__ float ex2f(float x) {
    float y; asm("ex2.approx.f32 %0, %1;" : "=f"(y) : "f"(x)); return y;
}
__device__ __forceinline__ float tf32r(float x) {
    uint32_t y; asm("cvt.rna.tf32.f32 %0, %1;" : "=r"(y) : "f"(x));
    return __uint_as_float(y);
}
__device__ __forceinline__ uint32_t s2u(const void* p) {
    uint32_t a;
    asm("{ .reg .u64 t; cvta.to.shared.u64 t, %1; cvt.u32.u64 %0, t; }" : "=r"(a) : "l"(p));
    return a;
}
__device__ __forceinline__ void cpa16(uint32_t saddr, const void* gaddr) {
    asm volatile("cp.async.cg.shared.global [%0], [%1], 16;" :: "r"(saddr), "l"(gaddr));
}
#define CPA_COMMIT() asm volatile("cp.async.commit_group;" ::: "memory")
#define CPA_WAIT0()  asm volatile("cp.async.wait_group 0;" ::: "memory")

// D = A(16x8,tf32,row) * B(8x8,tf32,col) + D  (fp32 accum)
__device__ __forceinline__ void mma8(float* c, const uint32_t* a, const uint32_t* b) {
    asm volatile(
        "mma.sync.aligned.m16n8k8.row.col.f32.tf32.tf32.f32 "
        "{%0,%1,%2,%3}, {%4,%5,%6,%7}, {%8,%9}, {%0,%1,%2,%3};"
        : "+f"(c[0]), "+f"(c[1]), "+f"(c[2]), "+f"(c[3])
        : "r"(a[0]), "r"(a[1]), "r"(a[2]), "r"(a[3]), "r"(b[0]), "r"(b[1]));
}

// ---- prologue: pre-round inputs to tf32 (Q also pre-scaled) ----
__global__ void prep(const float* __restrict__ Q, const float* __restrict__ K,
                     const float* __restrict__ V) {
    size_t idx = (size_t)blockIdx.x * blockDim.x + threadIdx.x;
    float4 q = ((const float4*)Q)[idx];
    q.x = tf32r(q.x * SCALE); q.y = tf32r(q.y * SCALE);
    q.z = tf32r(q.z * SCALE); q.w = tf32r(q.w * SCALE);
    ((float4*)Qr)[idx] = q;
    float4 k = ((const float4*)K)[idx];
    k.x = tf32r(k.x); k.y = tf32r(k.y); k.z = tf32r(k.z); k.w = tf32r(k.w);
    ((float4*)Kr)[idx] = k;
    float4 v = ((const float4*)V)[idx];
    v.x = tf32r(v.x); v.y = tf32r(v.y); v.z = tf32r(v.z); v.w = tf32r(v.w);
    ((float4*)Vr)[idx] = v;
}

__global__ __launch_bounds__(NT, 1)
void attn2(float* __restrict__ Wg, float* __restrict__ Og) {
    extern __shared__ float sm[];
    const uint32_t sb = s2u(sm);
    float* Qs = sm + QS_OFF;
    float* Ps = sm + PS_OFF;
    float* RS = sm + RS_OFF;

    const int tid  = threadIdx.x;
    const int warp = tid >> 5;
    const int lane = tid & 31;
    const int g    = lane >> 2;
    const int tig  = lane & 3;
    const int bh = blockIdx.y, qb = blockIdx.x * BM;

    const float* Qp = Qr + ((size_t)bh * S_ + qb) * D_;
    const float* Kp = Kr + (size_t)bh * S_ * D_;
    const float* Vp = Vr + (size_t)bh * S_ * D_;
    float* Wp = Wg + (size_t)bh * S_ * S_ + (size_t)qb * S_;
    float* Op = Og + ((size_t)bh * S_ + qb) * D_;

    auto cpaK = [&](int kt, uint32_t dst_off) {
        const char* Ktg = (const char*)(Kp + (size_t)kt * BN * D_);
        #pragma unroll
        for (int i = 0; i < 4; i++) {
            int idx = tid + i * NT;
            int r = idx >> 4, c4 = (idx & 15) * 4;
            cpa16(sb + (uint32_t)(dst_off + r * KP + c4) * 4, Ktg + (size_t)idx * 16);
        }
    };
    auto cpaV = [&](int kt, int vb) {
        const char* Vtg = (const char*)(Vp + (size_t)kt * BN * D_);
        #pragma unroll
        for (int i = 0; i < 4; i++) {
            int idx = tid + i * NT;
            int r = idx >> 4, c4 = (idx & 15) * 4;
            cpa16(sb + (uint32_t)(VS_OFF + vb * VSTRIDE + r * VP + c4) * 4,
                  Vtg + (size_t)idx * 16);
        }
    };

    // ---- load Q (already scaled+rounded) ----
    #pragma unroll
    for (int i = 0; i < 4; i++) {
        int idx = tid + i * NT;
        int r = idx >> 4, c4 = (idx & 15) * 4;
        *(float4*)(Qs + r * QP + c4) = ((const float4*)Qp)[idx];
    }

    const int mw  = warp & 3;         // 4 m-warps: 32 q rows each
    const int nw  = warp >> 2;        // 4 n-warps
    const int q0w = mw * 32;
    const int n0w = nw * 32;          // QK: 32 k-cols per warp
    const int d0w = nw * 16;          // PV: 16 d-cols per warp

    // =============== PASS 1: rowsums only ===============
    cpaK(0, KS_OFF); CPA_COMMIT();
    float rs1[2][2] = {{0.f, 0.f}, {0.f, 0.f}};

    for (int kt = 0; kt < NTILES; kt++) {
        CPA_WAIT0();
        __syncthreads();
        if (kt + 1 < NTILES) { cpaK(kt + 1, ((kt + 1) & 1) ? PS_OFF : KS_OFF); CPA_COMMIT(); }
        const float* kb = sm + ((kt & 1) ? PS_OFF : KS_OFF);

        float accS[2][4][4];
        #pragma unroll
        for (int mt = 0; mt < 2; mt++)
            #pragma unroll
            for (int nt = 0; nt < 4; nt++)
                #pragma unroll
                for (int i = 0; i < 4; i++) accS[mt][nt][i] = 0.f;

        #pragma unroll
        for (int ks = 0; ks < 8; ks++) {
            const int d = ks * 8;
            uint32_t A[2][4];
            #pragma unroll
            for (int mt = 0; mt < 2; mt++) {
                const int r0 = q0w + mt * 16 + g;
                A[mt][0] = __float_as_uint(Qs[r0 * QP + d + tig]);
                A[mt][1] = __float_as_uint(Qs[(r0 + 8) * QP + d + tig]);
                A[mt][2] = __float_as_uint(Qs[r0 * QP + d + tig + 4]);
                A[mt][3] = __float_as_uint(Qs[(r0 + 8) * QP + d + tig + 4]);
            }
            #pragma unroll
            for (int nt = 0; nt < 4; nt++) {
                const int n0 = n0w + nt * 8 + g;
                uint32_t B[2];
                B[0] = __float_as_uint(kb[n0 * KP + d + tig]);
                B[1] = __float_as_uint(kb[n0 * KP + d + tig + 4]);
                mma8(accS[0][nt], A[0], B);
                mma8(accS[1][nt], A[1], B);
            }
        }
        #pragma unroll
        for (int mt = 0; mt < 2; mt++)
            #pragma unroll
            for (int nt = 0; nt < 4; nt++) {
                rs1[mt][0] += ex2f(accS[mt][nt][0]) + ex2f(accS[mt][nt][1]);
                rs1[mt][1] += ex2f(accS[mt][nt][2]) + ex2f(accS[mt][nt][3]);
            }
    }

    // prefetch pass-2 tile 0 while reducing rowsums
    cpaK(0, KS_OFF); CPA_COMMIT();
    cpaV(0, 0);      CPA_COMMIT();

    #pragma unroll
    for (int mt = 0; mt < 2; mt++)
        #pragma unroll
        for (int h = 0; h < 2; h++) {
            float v = rs1[mt][h];
            v += __shfl_xor_sync(0xffffffffu, v, 1);
            v += __shfl_xor_sync(0xffffffffu, v, 2);
            rs1[mt][h] = v;
        }
    if (tig == 0) {
        #pragma unroll
        for (int mt = 0; mt < 2; mt++)
            #pragma unroll
            for (int h = 0; h < 2; h++)
                RS[nw * 128 + q0w + mt * 16 + g + h * 8] = rs1[mt][h];
    }
    __syncthreads();

    float inv[2][2];
    #pragma unroll
    for (int mt = 0; mt < 2; mt++)
        #pragma unroll
        for (int h = 0; h < 2; h++) {
            const int r = q0w + mt * 16 + g + h * 8;
            inv[mt][h] = 1.0f / (RS[r] + RS[128 + r] + RS[256 + r] + RS[384 + r]);
        }

    // =============== PASS 2: normalized W store + PV ===============
    float accO[2][2][4];
    #pragma unroll
    for (int mt = 0; mt < 2; mt++)
        #pragma unroll
        for (int nt = 0; nt < 2; nt++)
            #pragma unroll
            for (int i = 0; i < 4; i++) accO[mt][nt][i] = 0.f;

    for (int kt = 0; kt < NTILES; kt++) {
        CPA_WAIT0();            // K(kt) + V(kt) resident
        __syncthreads();
        if (kt + 1 < NTILES) { cpaV(kt + 1, (kt + 1) & 1); CPA_COMMIT(); }

        // ---- QK^T ----
        float accS[2][4][4];
        #pragma unroll
        for (int mt = 0; mt < 2; mt++)
            #pragma unroll
            for (int nt = 0; nt < 4; nt++)
                #pragma unroll
                for (int i = 0; i < 4; i++) accS[mt][nt][i] = 0.f;

        const float* kb = sm + KS_OFF;
        #pragma unroll
        for (int ks = 0; ks < 8; ks++) {
            const int d = ks * 8;
            uint32_t A[2][4];
            #pragma unroll
            for (int mt = 0; mt < 2; mt++) {
                const int r0 = q0w + mt * 16 + g;
                A[mt][0] = __float_as_uint(Qs[r0 * QP + d + tig]);
                A[mt][1] = __float_as_uint(Qs[(r0 + 8) * QP + d + tig]);
                A[mt][2] = __float_as_uint(Qs[r0 * QP + d + tig + 4]);
                A[mt][3] = __float_as_uint(Qs[(r0 + 8) * QP + d + tig + 4]);
            }
            #pragma unroll
            for (int nt = 0; nt < 4; nt++) {
                const int n0 = n0w + nt * 8 + g;
                uint32_t B[2];
                B[0] = __float_as_uint(kb[n0 * KP + d + tig]);
                B[1] = __float_as_uint(kb[n0 * KP + d + tig + 4]);
                mma8(accS[0][nt], A[0], B);
                mma8(accS[1][nt], A[1], B);
            }
        }
        __syncthreads();        // Ks reads done -> prefetch next K
        if (kt + 1 < NTILES) { cpaK(kt + 1, KS_OFF); CPA_COMMIT(); }

        // ---- epilogue: exp2, normalize, STG W once, STS P (tf32) ----
        const int kcol = kt * BN;
        #pragma unroll
        for (int mt = 0; mt < 2; mt++) {
            const int r0 = q0w + mt * 16 + g;
            #pragma unroll
            for (int nt = 0; nt < 4; nt++) {
                const float w0 = ex2f(accS[mt][nt][0]) * inv[mt][0];
                const float w1 = ex2f(accS[mt][nt][1]) * inv[mt][0];
                const float w2 = ex2f(accS[mt][nt][2]) * inv[mt][1];
                const float w3 = ex2f(accS[mt][nt][3]) * inv[mt][1];
                const int c = n0w + nt * 8 + tig * 2;
                *(float2*)(Wp + (size_t)r0 * S_ + kcol + c)       = make_float2(w0, w1);
                *(float2*)(Wp + (size_t)(r0 + 8) * S_ + kcol + c) = make_float2(w2, w3);
                *(float2*)(Ps + r0 * PP + c)       = make_float2(tf32r(w0), tf32r(w1));
                *(float2*)(Ps + (r0 + 8) * PP + c) = make_float2(tf32r(w2), tf32r(w3));
            }
        }
        __syncthreads();        // P visible to all n-warps

        // ---- PV: O[32q x 16d] += P[32q x 128k] @ V[128k x 16d] ----
        const float* vb = sm + VS_OFF + (kt & 1) * VSTRIDE;
        #pragma unroll
        for (int ks = 0; ks < 16; ks++) {
            const int kk = ks * 8;
            uint32_t A[2][4];
            #pragma unroll
            for (int mt = 0; mt < 2; mt++) {
                const int r0 = q0w + mt * 16 + g;
                A[mt][0] = __float_as_uint(Ps[r0 * PP + kk + tig]);
                A[mt][1] = __float_as_uint(Ps[(r0 + 8) * PP + kk + tig]);
                A[mt][2] = __float_as_uint(Ps[r0 * PP + kk + tig + 4]);
                A[mt][3] = __float_as_uint(Ps[(r0 + 8) * PP + kk + tig + 4]);
            }
            #pragma unroll
            for (int nt = 0; nt < 2; nt++) {
                const int n0 = d0w + nt * 8 + g;
                uint32_t B[2];
                B[0] = __float_as_uint(vb[(kk + tig) * VP + n0]);
                B[1] = __float_as_uint(vb[(kk + tig + 4) * VP + n0]);
                mma8(accO[0][nt], A[0], B);
                mma8(accO[1][nt], A[1], B);
            }
        }
    }

    // ---- O store (already normalized) ----
    #pragma unroll
    for (int mt = 0; mt < 2; mt++) {
        const int r0 = q0w + mt * 16 + g;
        #pragma unroll
        for (int nt = 0; nt < 2; nt++) {
            const int c = d0w + nt * 8 + tig * 2;
            *(float2*)(Op + (size_t)r0 * D_ + c) =
                make_float2(accO[mt][nt][0], accO[mt][nt][1]);
            *(float2*)(Op + (size_t)(r0 + 8) * D_ + c) =
                make_float2(accO[mt][nt][2], accO[mt][nt][3]);
        }
    }
}

extern "C" void kernel_launch(void* const* d_in, const int* in_sizes, int n_in,
                              void* d_out, int out_size) {
    const float* Q = (const float*)d_in[0];
    const float* K = (const float*)d_in[1];
    const float* V = (const float*)d_in[2];
    float* W = (float*)d_out;
    float* O = (float*)d_out + (size_t)NH * S_ * S_;

    const int smem_bytes = SMEM_FLOATS * (int)sizeof(float);
    cudaFuncSetAttribute(attn2, cudaFuncAttributeMaxDynamicSharedMemorySize, smem_bytes);

    const size_t n4 = (size_t)NH * S_ * D_ / 4;
    prep<<<(unsigned)(n4 / 256), 256>>>(Q, K, V);

    dim3 grid(S_ / BM, NH);
    attn2<<<grid, NT, smem_bytes>>>(W, O);
}

// round 17
// speedup vs baseline: 1.1973x; 1.1973x over previous
#include <cuda_runtime.h>
#include <cstdint>

#define S_    4096
#define D_    64
#define NH    16
#define BM    128
#define BN    128
#define NT    256
#define NTILES (S_/BN)
#define SCALE 0.18033688011112042f   // log2(e)/sqrt(64)

// smem pitches (floats)
#define QP 68
#define KP 68
#define VP 72
#define PP 132

// smem float offsets
#define QS_OFF 0            // Q  128*68 = 8704
#define KS_OFF 8704         // K  128*68 = 8704   (pass-2 K; pass-1 K buf A)
#define PS_OFF 17408        // P  128*132 = 16896 (pass-1 K buf B)
#define VS_OFF 34304        // V  2 x 128*72 = 18432
#define VSTRIDE 9216
#define RS_OFF 52736        // 2 x 128 rowsum partials
#define SMEM_FLOATS 52992   // 211968 B -> 1 CTA/SM

// pre-rounded inputs: Qr = rna(Q*SCALE), Kr/Vr = rna(K/V)
__device__ __align__(16) float Qr[(size_t)NH * S_ * D_];
__device__ __align__(16) float Kr[(size_t)NH * S_ * D_];
__device__ __align__(16) float Vr[(size_t)NH * S_ * D_];

__device__ __forceinline__ float ex2f(float x) {
    float y; asm("ex2.approx.f32 %0, %1;" : "=f"(y) : "f"(x)); return y;
}
__device__ __forceinline__ float tf32r(float x) {
    uint32_t y; asm("cvt.rna.tf32.f32 %0, %1;" : "=r"(y) : "f"(x));
    return __uint_as_float(y);
}
__device__ __forceinline__ uint32_t s2u(const void* p) {
    uint32_t a;
    asm("{ .reg .u64 t; cvta.to.shared.u64 t, %1; cvt.u32.u64 %0, t; }" : "=r"(a) : "l"(p));
    return a;
}
__device__ __forceinline__ void cpa16(uint32_t saddr, const void* gaddr) {
    asm volatile("cp.async.cg.shared.global [%0], [%1], 16;" :: "r"(saddr), "l"(gaddr));
}
#define CPA_COMMIT() asm volatile("cp.async.commit_group;" ::: "memory")
#define CPA_WAIT0()  asm volatile("cp.async.wait_group 0;" ::: "memory")

// D = A(16x8,tf32,row) * B(8x8,tf32,col) + D  (fp32 accum)
__device__ __forceinline__ void mma8(float* c, const uint32_t* a, const uint32_t* b) {
    asm volatile(
        "mma.sync.aligned.m16n8k8.row.col.f32.tf32.tf32.f32 "
        "{%0,%1,%2,%3}, {%4,%5,%6,%7}, {%8,%9}, {%0,%1,%2,%3};"
        : "+f"(c[0]), "+f"(c[1]), "+f"(c[2]), "+f"(c[3])
        : "r"(a[0]), "r"(a[1]), "r"(a[2]), "r"(a[3]), "r"(b[0]), "r"(b[1]));
}

// ---- prologue: pre-round inputs to tf32 (Q also pre-scaled) ----
__global__ void prep(const float* __restrict__ Q, const float* __restrict__ K,
                     const float* __restrict__ V) {
    size_t idx = (size_t)blockIdx.x * blockDim.x + threadIdx.x;
    float4 q = ((const float4*)Q)[idx];
    q.x = tf32r(q.x * SCALE); q.y = tf32r(q.y * SCALE);
    q.z = tf32r(q.z * SCALE); q.w = tf32r(q.w * SCALE);
    ((float4*)Qr)[idx] = q;
    float4 k = ((const float4*)K)[idx];
    k.x = tf32r(k.x); k.y = tf32r(k.y); k.z = tf32r(k.z); k.w = tf32r(k.w);
    ((float4*)Kr)[idx] = k;
    float4 v = ((const float4*)V)[idx];
    v.x = tf32r(v.x); v.y = tf32r(v.y); v.z = tf32r(v.z); v.w = tf32r(v.w);
    ((float4*)Vr)[idx] = v;
}

__global__ __launch_bounds__(NT, 1)
void attn2(float* __restrict__ Wg, float* __restrict__ Og) {
    extern __shared__ float sm[];
    const uint32_t sb = s2u(sm);
    float* Qs = sm + QS_OFF;
    float* Ps = sm + PS_OFF;
    float* RS = sm + RS_OFF;

    const int tid  = threadIdx.x;
    const int warp = tid >> 5;
    const int lane = tid & 31;
    const int g    = lane >> 2;
    const int tig  = lane & 3;
    const int bh = blockIdx.y, qb = blockIdx.x * BM;

    const float* Qp = Qr + ((size_t)bh * S_ + qb) * D_;
    const float* Kp = Kr + (size_t)bh * S_ * D_;
    const float* Vp = Vr + (size_t)bh * S_ * D_;
    float* Wp = Wg + (size_t)bh * S_ * S_ + (size_t)qb * S_;
    float* Op = Og + ((size_t)bh * S_ + qb) * D_;

    auto cpaK = [&](int kt, uint32_t dst_off) {
        const char* Ktg = (const char*)(Kp + (size_t)kt * BN * D_);
        #pragma unroll
        for (int i = 0; i < 8; i++) {
            int idx = tid + i * NT;
            int r = idx >> 4, c4 = (idx & 15) * 4;
            cpa16(sb + (uint32_t)(dst_off + r * KP + c4) * 4, Ktg + (size_t)idx * 16);
        }
    };
    auto cpaV = [&](int kt, int vb) {
        const char* Vtg = (const char*)(Vp + (size_t)kt * BN * D_);
        #pragma unroll
        for (int i = 0; i < 8; i++) {
            int idx = tid + i * NT;
            int r = idx >> 4, c4 = (idx & 15) * 4;
            cpa16(sb + (uint32_t)(VS_OFF + vb * VSTRIDE + r * VP + c4) * 4,
                  Vtg + (size_t)idx * 16);
        }
    };

    // ---- load Q (already scaled+rounded) into smem ----
    #pragma unroll
    for (int i = 0; i < 8; i++) {
        int idx = tid + i * NT;
        int r = idx >> 4, c4 = (idx & 15) * 4;
        *(float4*)(Qs + r * QP + c4) = ((const float4*)Qp)[idx];
    }

    const int mw  = warp & 3;
    const int nw  = warp >> 2;
    const int q0w = mw * 32;
    const int n0w = nw * 64;
    const int d0w = nw * 32;

    // ---- hoist Q fragments into registers (loop-invariant for whole kernel) ----
    __syncthreads();
    uint32_t Qf[8][2][4];
    #pragma unroll
    for (int ks = 0; ks < 8; ks++) {
        const int d = ks * 8;
        #pragma unroll
        for (int mt = 0; mt < 2; mt++) {
            const int r0 = q0w + mt * 16 + g;
            Qf[ks][mt][0] = __float_as_uint(Qs[r0 * QP + d + tig]);
            Qf[ks][mt][1] = __float_as_uint(Qs[(r0 + 8) * QP + d + tig]);
            Qf[ks][mt][2] = __float_as_uint(Qs[r0 * QP + d + tig + 4]);
            Qf[ks][mt][3] = __float_as_uint(Qs[(r0 + 8) * QP + d + tig + 4]);
        }
    }

    // =============== PASS 1: rowsums only ===============
    cpaK(0, KS_OFF); CPA_COMMIT();
    float rs1[2][2] = {{0.f, 0.f}, {0.f, 0.f}};

    for (int kt = 0; kt < NTILES; kt++) {
        CPA_WAIT0();
        __syncthreads();
        if (kt + 1 < NTILES) { cpaK(kt + 1, ((kt + 1) & 1) ? PS_OFF : KS_OFF); CPA_COMMIT(); }
        const float* kb = sm + ((kt & 1) ? PS_OFF : KS_OFF);

        #pragma unroll
        for (int h = 0; h < 2; h++) {
            float accS[2][4][4];
            #pragma unroll
            for (int mt = 0; mt < 2; mt++)
                #pragma unroll
                for (int nt = 0; nt < 4; nt++)
                    #pragma unroll
                    for (int i = 0; i < 4; i++) accS[mt][nt][i] = 0.f;

            #pragma unroll
            for (int ks = 0; ks < 8; ks++) {
                const int d = ks * 8;
                #pragma unroll
                for (int nt = 0; nt < 4; nt++) {
                    const int n0 = n0w + h * 32 + nt * 8 + g;
                    uint32_t B[2];
                    B[0] = __float_as_uint(kb[n0 * KP + d + tig]);
                    B[1] = __float_as_uint(kb[n0 * KP + d + tig + 4]);
                    mma8(accS[0][nt], Qf[ks][0], B);
                    mma8(accS[1][nt], Qf[ks][1], B);
                }
            }
            #pragma unroll
            for (int mt = 0; mt < 2; mt++)
                #pragma unroll
                for (int nt = 0; nt < 4; nt++) {
                    rs1[mt][0] += ex2f(accS[mt][nt][0]) + ex2f(accS[mt][nt][1]);
                    rs1[mt][1] += ex2f(accS[mt][nt][2]) + ex2f(accS[mt][nt][3]);
                }
        }
    }

    // prefetch pass-2 tile 0 while reducing rowsums
    cpaK(0, KS_OFF); CPA_COMMIT();
    cpaV(0, 0);      CPA_COMMIT();

    #pragma unroll
    for (int mt = 0; mt < 2; mt++)
        #pragma unroll
        for (int h = 0; h < 2; h++) {
            float v = rs1[mt][h];
            v += __shfl_xor_sync(0xffffffffu, v, 1);
            v += __shfl_xor_sync(0xffffffffu, v, 2);
            rs1[mt][h] = v;
        }
    if (tig == 0) {
        #pragma unroll
        for (int mt = 0; mt < 2; mt++)
            #pragma unroll
            for (int h = 0; h < 2; h++)
                RS[nw * 128 + q0w + mt * 16 + g + h * 8] = rs1[mt][h];
    }
    __syncthreads();

    float inv[2][2];
    #pragma unroll
    for (int mt = 0; mt < 2; mt++)
        #pragma unroll
        for (int h = 0; h < 2; h++) {
            const int r = q0w + mt * 16 + g + h * 8;
            inv[mt][h] = 1.0f / (RS[r] + RS[128 + r]);
        }

    // =============== PASS 2: normalized W store + PV ===============
    float accO[2][4][4];
    #pragma unroll
    for (int mt = 0; mt < 2; mt++)
        #pragma unroll
        for (int nt = 0; nt < 4; nt++)
            #pragma unroll
            for (int i = 0; i < 4; i++) accO[mt][nt][i] = 0.f;

    for (int kt = 0; kt < NTILES; kt++) {
        CPA_WAIT0();            // K(kt) + V(kt) resident
        __syncthreads();
        if (kt + 1 < NTILES) { cpaV(kt + 1, (kt + 1) & 1); CPA_COMMIT(); }

        const float* kb = sm + KS_OFF;
        const int kcol = kt * BN;

        // ---- QK^T + epilogue, two nt-halves ----
        #pragma unroll
        for (int h = 0; h < 2; h++) {
            float accS[2][4][4];
            #pragma unroll
            for (int mt = 0; mt < 2; mt++)
                #pragma unroll
                for (int nt = 0; nt < 4; nt++)
                    #pragma unroll
                    for (int i = 0; i < 4; i++) accS[mt][nt][i] = 0.f;

            #pragma unroll
            for (int ks = 0; ks < 8; ks++) {
                const int d = ks * 8;
                #pragma unroll
                for (int nt = 0; nt < 4; nt++) {
                    const int n0 = n0w + h * 32 + nt * 8 + g;
                    uint32_t B[2];
                    B[0] = __float_as_uint(kb[n0 * KP + d + tig]);
                    B[1] = __float_as_uint(kb[n0 * KP + d + tig + 4]);
                    mma8(accS[0][nt], Qf[ks][0], B);
                    mma8(accS[1][nt], Qf[ks][1], B);
                }
            }

            // epilogue for this half: exp2, normalize, STG W once, STS P (tf32)
            #pragma unroll
            for (int mt = 0; mt < 2; mt++) {
                const int r0 = q0w + mt * 16 + g;
                #pragma unroll
                for (int nt = 0; nt < 4; nt++) {
                    const float w0 = ex2f(accS[mt][nt][0]) * inv[mt][0];
                    const float w1 = ex2f(accS[mt][nt][1]) * inv[mt][0];
                    const float w2 = ex2f(accS[mt][nt][2]) * inv[mt][1];
                    const float w3 = ex2f(accS[mt][nt][3]) * inv[mt][1];
                    const int c = n0w + h * 32 + nt * 8 + tig * 2;
                    *(float2*)(Wp + (size_t)r0 * S_ + kcol + c)       = make_float2(w0, w1);
                    *(float2*)(Wp + (size_t)(r0 + 8) * S_ + kcol + c) = make_float2(w2, w3);
                    *(float2*)(Ps + r0 * PP + c)       = make_float2(tf32r(w0), tf32r(w1));
                    *(float2*)(Ps + (r0 + 8) * PP + c) = make_float2(tf32r(w2), tf32r(w3));
                }
            }
        }
        __syncthreads();        // Ks reads + Ps writes complete
        if (kt + 1 < NTILES) { cpaK(kt + 1, KS_OFF); CPA_COMMIT(); }

        // ---- PV: O[32q x 32d] += P[32q x 128k] @ V[128k x 32d] ----
        const float* vb = sm + VS_OFF + (kt & 1) * VSTRIDE;
        #pragma unroll
        for (int ks = 0; ks < 16; ks++) {
            const int kk = ks * 8;
            uint32_t A[2][4];
            #pragma unroll
            for (int mt = 0; mt < 2; mt++) {
                const int r0 = q0w + mt * 16 + g;
                A[mt][0] = __float_as_uint(Ps[r0 * PP + kk + tig]);
                A[mt][1] = __float_as_uint(Ps[(r0 + 8) * PP + kk + tig]);
                A[mt][2] = __float_as_uint(Ps[r0 * PP + kk + tig + 4]);
                A[mt][3] = __float_as_uint(Ps[(r0 + 8) * PP + kk + tig + 4]);
            }
            #pragma unroll
            for (int nt = 0; nt < 4; nt++) {
                const int n0 = d0w + nt * 8 + g;
                uint32_t B[2];
                B[0] = __float_as_uint(vb[(kk + tig) * VP + n0]);
                B[1] = __float_as_uint(vb[(kk + tig + 4) * VP + n0]);
                mma8(accO[0][nt], A[0], B);
                mma8(accO[1][nt], A[1], B);
            }
        }
    }

    // ---- O store (already normalized) ----
    #pragma unroll
    for (int mt = 0; mt < 2; mt++) {
        const int r0 = q0w + mt * 16 + g;
        #pragma unroll
        for (int nt = 0; nt < 4; nt++) {
            const int c = d0w + nt * 8 + tig * 2;
            *(float2*)(Op + (size_t)r0 * D_ + c) =
                make_float2(accO[mt][nt][0], accO[mt][nt][1]);
            *(float2*)(Op + (size_t)(r0 + 8) * D_ + c) =
                make_float2(accO[mt][nt][2], accO[mt][nt][3]);
        }
    }
}

extern "C" void kernel_launch(void* const* d_in, const int* in_sizes, int n_in,
                              void* d_out, int out_size) {
    const float* Q = (const float*)d_in[0];
    const float* K = (const float*)d_in[1];
    const float* V = (const float*)d_in[2];
    float* W = (float*)d_out;
    float* O = (float*)d_out + (size_t)NH * S_ * S_;

    const int smem_bytes = SMEM_FLOATS * (int)sizeof(float);
    cudaFuncSetAttribute(attn2, cudaFuncAttributeMaxDynamicSharedMemorySize, smem_bytes);

    const size_t n4 = (size_t)NH * S_ * D_ / 4;
    prep<<<(unsigned)(n4 / 256), 256>>>(Q, K, V);

    dim3 grid(S_ / BM, NH);
    attn2<<<grid, NT, smem_bytes>>>(W, O);
}